// round 11
// baseline (speedup 1.0000x reference)
#include <cuda_runtime.h>
#include <cuda_fp16.h>
#include <math.h>
#include <stdint.h>

// Problem constants
#define SLEN 1024
#define BSZ  8
#define IDIM 256
#define HDIM 512
#define NHEAD 8
#define HD 64
#define FFDIM 1024
#define NLAYER 4
#define NTOK (SLEN*BSZ)   // 8192

// ---------------- scratch (device globals; no allocation allowed) -----------
__device__ __half g_xin [NTOK * IDIM];    // fp16
__device__ float  g_x   [NTOK * HDIM];    // fp32 (residual stream)
__device__ __half g_xc  [NTOK * HDIM];    // fp16 copy of x
__device__ float  g_tmp [NTOK * HDIM];    // fp32
__device__ __half g_qkvh[NTOK * 1536];    // fp16 Q|K|V
__device__ __half g_attn[NTOK * HDIM];    // fp16
__device__ __half g_ff  [NTOK * FFDIM];   // fp16
__device__ __half g_w   [8519680];        // all weights, fp16
__device__ uint32_t g_mask[3 * BSZ * SLEN * 32];  // packed allow-bits per class

// weight offsets in g_w (halves)
#define OFF_DENSE 0
#define OFF_QKV   131072
#define OFF_OUT   3276800
#define OFF_FF1   4325376
#define OFF_FF2   6422528

// ---------------- helpers ---------------------------------------------------
// fp16 mma: k=16, fp32 accumulate
__device__ __forceinline__ void mma16h(float* c, const uint32_t* a, uint32_t b0, uint32_t b1){
    asm volatile(
        "mma.sync.aligned.m16n8k16.row.col.f32.f16.f16.f32 "
        "{%0,%1,%2,%3},{%4,%5,%6,%7},{%8,%9},{%0,%1,%2,%3};"
        : "+f"(c[0]),"+f"(c[1]),"+f"(c[2]),"+f"(c[3])
        : "r"(a[0]),"r"(a[1]),"r"(a[2]),"r"(a[3]),"r"(b0),"r"(b1));
}
__device__ __forceinline__ void ldsm4t(uint32_t& r0, uint32_t& r1, uint32_t& r2, uint32_t& r3,
                                       uint32_t addr){
    asm volatile("ldmatrix.sync.aligned.m8n8.x4.trans.shared.b16 {%0,%1,%2,%3}, [%4];"
        : "=r"(r0),"=r"(r1),"=r"(r2),"=r"(r3) : "r"(addr));
}
__device__ __forceinline__ void cpa16(uint32_t s, const void* g){
    asm volatile("cp.async.cg.shared.global [%0], [%1], 16;" :: "r"(s),"l"(g));
}
__device__ __forceinline__ void cpacommit(){ asm volatile("cp.async.commit_group;"); }
__device__ __forceinline__ void cpawait1(){ asm volatile("cp.async.wait_group 1;"); }
__device__ __forceinline__ void cpawait0(){ asm volatile("cp.async.wait_group 0;"); }

// ---------------- all-weights fp16 conversion (one launch) ------------------
__global__ void cvt_all_kernel(const float4* __restrict__ s0, const float4* __restrict__ s1,
                               const float4* __restrict__ s2, const float4* __restrict__ s3,
                               const float4* __restrict__ s4, uint2* __restrict__ dst)
{
    int i = blockIdx.x * 256 + threadIdx.x;
    if (i >= 2129920) return;
    const float4* src;
    if      (i <   32768) src = s0 + i;
    else if (i <  819200) src = s1 + (i - 32768);
    else if (i < 1081344) src = s2 + (i - 819200);
    else if (i < 1605632) src = s3 + (i - 1081344);
    else                  src = s4 + (i - 1605632);
    float4 v = *src;
    __half2 h0 = __floats2half2_rn(v.x, v.y);
    __half2 h1 = __floats2half2_rn(v.z, v.w);
    uint2 o;
    o.x = *(uint32_t*)&h0;
    o.y = *(uint32_t*)&h1;
    dst[i] = o;
}

// ---------------- mask bit precompute ---------------------------------------
__global__ void mask_kernel(const int* __restrict__ dist, uint32_t* __restrict__ mask)
{
    int b = blockIdx.y;
    int q = blockIdx.x * 8 + (threadIdx.x >> 5);
    int w = threadIdx.x & 31;
    const int4* dr = (const int4*)(dist + ((size_t)b*SLEN + q)*SLEN + w*32);
    const int4* d0 = (const int4*)(dist + (size_t)b*SLEN*SLEN + w*32);
    uint32_t sb = 0, lb = 0, gb = 0;
#pragma unroll
    for (int p = 0; p < 8; p++){
        int4 d = dr[p], dg = d0[p];
        int j = p*4;
        sb |= (uint32_t)(d.x==1)<<j | (uint32_t)(d.y==1)<<(j+1)
            | (uint32_t)(d.z==1)<<(j+2) | (uint32_t)(d.w==1)<<(j+3);
        lb |= (uint32_t)(d.x>=1)<<j | (uint32_t)(d.y>=1)<<(j+1)
            | (uint32_t)(d.z>=1)<<(j+2) | (uint32_t)(d.w>=1)<<(j+3);
        gb |= (uint32_t)(dg.x>=1)<<j | (uint32_t)(dg.y>=1)<<(j+1)
            | (uint32_t)(dg.z>=1)<<(j+2) | (uint32_t)(dg.w>=1)<<(j+3);
    }
    if ((q >> 5) == w){ uint32_t e = 1u << (q & 31); sb |= e; lb |= e; gb |= e; }
    size_t o = ((size_t)b*SLEN + q)*32 + w;
    mask[o] = sb;
    mask[(size_t)BSZ*SLEN*32 + o] = lb;
    mask[(size_t)2*BSZ*SLEN*32 + o] = gb;
}

// ---------------- transpose nodes (S,B,I) -> x_in (B*S, I), fp16 ------------
__global__ void transpose_kernel(const float* __restrict__ nodes, __half* __restrict__ xin)
{
    int token = blockIdx.x;
    int b = token >> 10;
    int s = token & 1023;
    float v = nodes[((size_t)s * BSZ + b) * IDIM + threadIdx.x];
    xin[(size_t)token * IDIM + threadIdx.x] = __float2half_rn(v);
}

// ---------------- fp16 tensor-core GEMM: C[M,N] = A[M,K] @ W[N,K]^T + bias --
// CTA 128x128, BK=64 halves, 256 threads = 8 warps (2m x 4n), warp tile 64x32.
// flags: bit0 relu, bit2 store fp16 (else fp32).
__global__ __launch_bounds__(256,2) void gemm_f16(
    const __half* __restrict__ A, const __half* __restrict__ W,
    const float* __restrict__ bias, void* __restrict__ Cv,
    int M, int N, int K, int flags)
{
    extern __shared__ uint32_t smu[];
    uint32_t* sA = smu;             // 2 stages * 4608 u32
    uint32_t* sB = smu + 9216;      // 2 stages * 4608 u32

    const int tid  = threadIdx.x;
    const int lane = tid & 31, wid = tid >> 5;
    const int g = lane >> 2, r = lane & 3;
    const int wm = wid & 1, wn = wid >> 1;
    const int row0 = blockIdx.y * 128, col0 = blockIdx.x * 128;

    const uint32_t sAb = (uint32_t)__cvta_generic_to_shared(sA);
    const uint32_t sBb = (uint32_t)__cvta_generic_to_shared(sB);

    float c[4][4][4];
#pragma unroll
    for (int i=0;i<4;i++)
#pragma unroll
        for (int j=0;j<4;j++)
#pragma unroll
            for (int k=0;k<4;k++) c[i][j][k] = 0.f;

    const int nbk = K >> 6;

    auto issue = [&](int bk, int st){
#pragma unroll
        for (int p=0;p<4;p++){
            int idx = tid + p*256;
            int row = idx >> 3, c4 = (idx & 7) << 2;
            cpa16(sAb + (uint32_t)(st*4608 + row*36 + c4)*4,
                  A + (size_t)(row0 + row)*K + bk*64 + c4*2);
            cpa16(sBb + (uint32_t)(st*4608 + row*36 + c4)*4,
                  W + (size_t)(col0 + row)*K + bk*64 + c4*2);
        }
        cpacommit();
    };

    issue(0, 0);
    for (int bk = 0; bk < nbk; bk++){
        int st = bk & 1;
        if (bk+1 < nbk){ issue(bk+1, st^1); cpawait1(); }
        else           { cpawait0(); }
        __syncthreads();
        const uint32_t* a_s = sA + st*4608;
        const uint32_t* b_s = sB + st*4608;
#pragma unroll
        for (int kc=0; kc<4; kc++){
            uint32_t a[4][4];
#pragma unroll
            for (int mt=0; mt<4; mt++){
                int mb = wm*64 + mt*16;
                a[mt][0] = a_s[(mb+g  )*36 + kc*8 + r  ];
                a[mt][1] = a_s[(mb+g+8)*36 + kc*8 + r  ];
                a[mt][2] = a_s[(mb+g  )*36 + kc*8 + r+4];
                a[mt][3] = a_s[(mb+g+8)*36 + kc*8 + r+4];
            }
#pragma unroll
            for (int nt=0; nt<4; nt++){
                int nb = wn*32 + nt*8;
                uint32_t b0 = b_s[(nb+g)*36 + kc*8 + r  ];
                uint32_t b1 = b_s[(nb+g)*36 + kc*8 + r+4];
#pragma unroll
                for (int mt=0; mt<4; mt++) mma16h(c[mt][nt], a[mt], b0, b1);
            }
        }
        __syncthreads();
    }

    const int relu = flags & 1, hfo = flags & 4;
#pragma unroll
    for (int mt=0; mt<4; mt++){
#pragma unroll
        for (int nt=0; nt<4; nt++){
            int rr = row0 + wm*64 + mt*16 + g;
            int cc = col0 + wn*32 + nt*8 + 2*r;
            float b0 = bias[cc], b1 = bias[cc+1];
            float v0 = c[mt][nt][0] + b0, v1 = c[mt][nt][1] + b1;
            float v2 = c[mt][nt][2] + b0, v3 = c[mt][nt][3] + b1;
            if (relu){ v0=fmaxf(v0,0.f); v1=fmaxf(v1,0.f); v2=fmaxf(v2,0.f); v3=fmaxf(v3,0.f); }
            if (hfo){
                __half* Ch = (__half*)Cv;
                *(__half2*)(Ch + (size_t)rr*N + cc)     = __floats2half2_rn(v0, v1);
                *(__half2*)(Ch + (size_t)(rr+8)*N + cc) = __floats2half2_rn(v2, v3);
            } else {
                float* Cf = (float*)Cv;
                *(float2*)(Cf + (size_t)rr*N + cc)     = make_float2(v0, v1);
                *(float2*)(Cf + (size_t)(rr+8)*N + cc) = make_float2(v2, v3);
            }
        }
    }
}

// ---------------- LayerNorm row kernel (H=512), optional residual -----------
__global__ __launch_bounds__(256) void ln_kernel(
    const float* __restrict__ y, const float* __restrict__ res,
    const float* __restrict__ g, const float* __restrict__ bta,
    float* __restrict__ out, __half* __restrict__ outc)
{
    __shared__ float rs[8], rq[8], stats[2];
    int tid = threadIdx.x;
    int lane = tid & 31, wid = tid >> 5;
    size_t base = (size_t)blockIdx.x * HDIM;

    float v0 = y[base + tid];
    float v1 = y[base + tid + 256];
    if (res) { v0 += res[base + tid]; v1 += res[base + tid + 256]; }

    float sum = v0 + v1;
    float sq  = v0 * v0 + v1 * v1;
#pragma unroll
    for (int off = 16; off > 0; off >>= 1) {
        sum += __shfl_xor_sync(0xffffffffu, sum, off);
        sq  += __shfl_xor_sync(0xffffffffu, sq,  off);
    }
    if (lane == 0) { rs[wid] = sum; rq[wid] = sq; }
    __syncthreads();
    if (tid == 0) {
        float S = 0.f, Q = 0.f;
#pragma unroll
        for (int i = 0; i < 8; i++) { S += rs[i]; Q += rq[i]; }
        float mean = S * (1.0f / HDIM);
        float var  = Q * (1.0f / HDIM) - mean * mean;
        stats[0] = mean;
        stats[1] = rsqrtf(var + 1e-5f);
    }
    __syncthreads();
    float mean = stats[0], inv = stats[1];
    float o0 = (v0 - mean) * inv * g[tid]       + bta[tid];
    float o1 = (v1 - mean) * inv * g[tid + 256] + bta[tid + 256];
    out[base + tid]        = o0;
    out[base + tid + 256]  = o1;
    outc[base + tid]       = __float2half_rn(o0);
    outc[base + tid + 256] = __float2half_rn(o1);
}

// ---------------- flash attention: all-fp16 mma, fp32 softmax ---------------
// CTA: 128 q-rows, k-tiles of 128. 512 threads = 16 warps (8m x 2n).
// smem (u32): Qs[128][36], Ks[128][36], Vs[128][36] (fp16 rows: 64 halves + pad),
//             Ms[128][68] (P as half2 words), msku, reductions.
__global__ __launch_bounds__(512,1) void attn_f16(
    const __half* __restrict__ qkvh, const uint32_t* __restrict__ maskall,
    __half* __restrict__ out)
{
    extern __shared__ uint32_t smx[];
    uint32_t* Qsu = smx;                      // 4608
    uint32_t* Ksu = smx + 4608;               // 4608
    uint32_t* Vsu = smx + 9216;               // 4608
    uint32_t* Msu = smx + 13824;              // 8704
    uint32_t* msku = smx + 22528;             // 512
    float* redm = (float*)(smx + 23040);      // 256
    float* reds = redm + 256;                 // 256
    float* rowM = reds + 256;                 // 128
    float* rowL = rowM + 128;                 // 128
    float* rowC = rowL + 128;                 // 128

    const int tid  = threadIdx.x;
    const int lane = tid & 31, wid = tid >> 5;
    const int g = lane >> 2, r = lane & 3;
    const int wm = wid & 7, wn = wid >> 3;
    const int q0 = blockIdx.x * 128, h = blockIdx.y, b = blockIdx.z;
    const size_t tokbase = (size_t)b * SLEN;
    const int qlo = wm*16 + g, qhi = qlo + 8;

    const int cls = (h < 4) ? 0 : (h < 6) ? 1 : 2;
    const uint32_t* mbase = maskall + (size_t)cls*BSZ*SLEN*32 + (size_t)b*SLEN*32;

    const uint32_t Qb = (uint32_t)__cvta_generic_to_shared(Qsu);
    const uint32_t Kb = (uint32_t)__cvta_generic_to_shared(Ksu);
    const uint32_t Vb = (uint32_t)__cvta_generic_to_shared(Vsu);

    // Q tile + K(0): 128 rows x 8 16B-chunks each
#pragma unroll
    for (int p=0;p<2;p++){
        int i = tid + p*512;
        int row = i >> 3, ch = i & 7;
        cpa16(Qb + (uint32_t)(row*36 + ch*4)*4,
              qkvh + (tokbase + q0 + row)*1536 + h*64 + ch*8);
        cpa16(Kb + (uint32_t)(row*36 + ch*4)*4,
              qkvh + (tokbase + row)*1536 + 512 + h*64 + ch*8);
    }
    cpacommit();
    if (tid < 128){ rowM[tid] = -1e30f; rowL[tid] = 0.f; }
    cpawait0();
    __syncthreads();

    // Q fragments, scaled by 1/sqrt(64) (exact exponent shift in fp16)
    const __half2 hs = __float2half2_rn(0.125f);
    uint32_t qa[4][4];
#pragma unroll
    for (int kc=0; kc<4; kc++){
#pragma unroll
        for (int j=0; j<4; j++){
            int rowq = (j & 1) ? qhi : qlo;
            int kk = kc*8 + r + ((j >> 1) ? 4 : 0);
            uint32_t u = Qsu[rowq*36 + kk];
            __half2 v = __hmul2(*(__half2*)&u, hs);
            qa[kc][j] = *(uint32_t*)&v;
        }
    }

    float o[4][4];
#pragma unroll
    for (int i=0;i<4;i++)
#pragma unroll
        for (int j=0;j<4;j++) o[i][j] = 0.f;

    for (int t = 0; t < 8; t++){
        const int k0 = t * 128;

        msku[tid] = mbase[(size_t)(q0 + (tid >> 2))*32 + t*4 + (tid & 3)];

        // scores S[128x128] via fp16 mma (K(t) in Ksu)
        float s[8][4];
#pragma unroll
        for (int i=0;i<8;i++)
#pragma unroll
            for (int j=0;j<4;j++) s[i][j] = 0.f;
#pragma unroll
        for (int kc=0; kc<4; kc++){
#pragma unroll
            for (int nt=0; nt<8; nt++){
                int nb = wn*64 + nt*8;
                uint32_t b0 = Ksu[(nb+g)*36 + kc*8 + r  ];
                uint32_t b1 = Ksu[(nb+g)*36 + kc*8 + r+4];
                mma16h(s[nt], qa[kc], b0, b1);
            }
        }
        __syncthreads();   // S done (Ksu free), prev PV done (Vsu/Msu free), msku visible

        // prefetch V(t) and K(t+1) behind softmax
#pragma unroll
        for (int p=0;p<2;p++){
            int i = tid + p*512;
            int row = i >> 3, ch = i & 7;
            cpa16(Vb + (uint32_t)(row*36 + ch*4)*4,
                  qkvh + (tokbase + k0 + row)*1536 + 1024 + h*64 + ch*8);
        }
        if (t < 7){
#pragma unroll
            for (int p=0;p<2;p++){
                int i = tid + p*512;
                int row = i >> 3, ch = i & 7;
                cpa16(Kb + (uint32_t)(row*36 + ch*4)*4,
                      qkvh + (tokbase + k0 + 128 + row)*1536 + 512 + h*64 + ch*8);
            }
        }
        cpacommit();

        // mask apply (bit test) + per-row tile max
        uint32_t wl0 = msku[qlo*4 + wn*2], wl1 = msku[qlo*4 + wn*2 + 1];
        uint32_t wh0 = msku[qhi*4 + wn*2], wh1 = msku[qhi*4 + wn*2 + 1];
        float mx0 = -1e30f, mx1 = -1e30f;
#pragma unroll
        for (int nt=0; nt<8; nt++){
            uint32_t wlo = (nt < 4) ? wl0 : wl1;
            uint32_t whi = (nt < 4) ? wh0 : wh1;
            int sh = (nt & 3)*8 + 2*r;
            s[nt][0] = ((wlo >> sh)     & 1) ? s[nt][0] : -1e9f;
            s[nt][1] = ((wlo >> (sh+1)) & 1) ? s[nt][1] : -1e9f;
            s[nt][2] = ((whi >> sh)     & 1) ? s[nt][2] : -1e9f;
            s[nt][3] = ((whi >> (sh+1)) & 1) ? s[nt][3] : -1e9f;
            mx0 = fmaxf(mx0, fmaxf(s[nt][0], s[nt][1]));
            mx1 = fmaxf(mx1, fmaxf(s[nt][2], s[nt][3]));
        }
        mx0 = fmaxf(mx0, __shfl_xor_sync(0xffffffffu, mx0, 1));
        mx0 = fmaxf(mx0, __shfl_xor_sync(0xffffffffu, mx0, 2));
        mx1 = fmaxf(mx1, __shfl_xor_sync(0xffffffffu, mx1, 1));
        mx1 = fmaxf(mx1, __shfl_xor_sync(0xffffffffu, mx1, 2));
        if (r == 0){ redm[qlo*2 + wn] = mx0; redm[qhi*2 + wn] = mx1; }
        __syncthreads();
        if (tid < 128){
            float mo = rowM[tid];
            float mn = fmaxf(mo, fmaxf(redm[tid*2], redm[tid*2+1]));
            rowC[tid] = __expf(mo - mn);
            rowM[tid] = mn;
        }
        __syncthreads();

        // exp, write P (fp16 half2) to Ms, partial sums
        float mlo = rowM[qlo], mhi = rowM[qhi];
        float ps0 = 0.f, ps1 = 0.f;
#pragma unroll
        for (int nt=0; nt<8; nt++){
            int wofs = wn*32 + nt*4 + r;       // u32 word index within row
            float p0 = __expf(s[nt][0]-mlo), p1 = __expf(s[nt][1]-mlo);
            float p2 = __expf(s[nt][2]-mhi), p3 = __expf(s[nt][3]-mhi);
            ps0 += p0 + p1;  ps1 += p2 + p3;
            __half2 hl = __floats2half2_rn(p0, p1);
            __half2 hh = __floats2half2_rn(p2, p3);
            Msu[qlo*68 + wofs] = *(uint32_t*)&hl;
            Msu[qhi*68 + wofs] = *(uint32_t*)&hh;
        }
        ps0 += __shfl_xor_sync(0xffffffffu, ps0, 1);
        ps0 += __shfl_xor_sync(0xffffffffu, ps0, 2);
        ps1 += __shfl_xor_sync(0xffffffffu, ps1, 1);
        ps1 += __shfl_xor_sync(0xffffffffu, ps1, 2);
        if (r == 0){ reds[qlo*2 + wn] = ps0; reds[qhi*2 + wn] = ps1; }

        // rescale O accumulators
        float clo = rowC[qlo], chi = rowC[qhi];
#pragma unroll
        for (int nt=0; nt<4; nt++){
            o[nt][0] *= clo; o[nt][1] *= clo;
            o[nt][2] *= chi; o[nt][3] *= chi;
        }
        cpawait0();        // V(t) and K(t+1) resident
        __syncthreads();   // V + P + reds visible
        if (tid < 128) rowL[tid] = rowL[tid]*rowC[tid] + reds[tid*2] + reds[tid*2+1];

        // O += P @ V : fp16 mma, B-frags via ldmatrix.trans on V[k][d]
        const int lr = lane & 7, tt = lane >> 3;
#pragma unroll
        for (int kc=0; kc<8; kc++){
            uint32_t pa[4];
            pa[0] = Msu[qlo*68 + kc*8 + r  ];
            pa[1] = Msu[qhi*68 + kc*8 + r  ];
            pa[2] = Msu[qlo*68 + kc*8 + r+4];
            pa[3] = Msu[qhi*68 + kc*8 + r+4];
#pragma unroll
            for (int pr=0; pr<2; pr++){
                int kr = kc*16 + (tt & 1)*8 + lr;
                int dc = wn*32 + pr*16 + (tt >> 1)*8;   // half-column
                uint32_t addr = Vb + (uint32_t)(kr*36 + (dc >> 1))*4;
                uint32_t b0, b1, b2, b3;
                ldsm4t(b0, b1, b2, b3, addr);
                mma16h(o[pr*2],   pa, b0, b1);
                mma16h(o[pr*2+1], pa, b2, b3);
            }
        }
    }
    __syncthreads();

    float llo = 1.f / rowL[qlo];
    float lhi = 1.f / rowL[qhi];
    size_t rlo = (tokbase + q0 + qlo) * HDIM;
    size_t rhi = (tokbase + q0 + qhi) * HDIM;
#pragma unroll
    for (int nt=0; nt<4; nt++){
        int cc = h*64 + wn*32 + nt*8 + 2*r;
        *(__half2*)(out + rlo + cc) = __floats2half2_rn(o[nt][0]*llo, o[nt][1]*llo);
        *(__half2*)(out + rhi + cc) = __floats2half2_rn(o[nt][2]*lhi, o[nt][3]*lhi);
    }
}

// ---------------- final batchnorm over batch of 8 at s=0 --------------------
__global__ void bn_kernel(const float* __restrict__ x, const float* __restrict__ g,
                          const float* __restrict__ bta, float* __restrict__ out)
{
    int c = threadIdx.x;
    float v[BSZ];
    float s = 0.f;
#pragma unroll
    for (int b = 0; b < BSZ; b++) {
        v[b] = x[((size_t)b * SLEN) * HDIM + c];
        s += v[b];
    }
    float mean = s * (1.0f / BSZ);
    float q = 0.f;
#pragma unroll
    for (int b = 0; b < BSZ; b++) { float d = v[b] - mean; q += d * d; }
    float inv = rsqrtf(q * (1.0f / BSZ) + 1e-5f);
#pragma unroll
    for (int b = 0; b < BSZ; b++)
        out[b * HDIM + c] = (v[b] - mean) * inv * g[c] + bta[c];
}

// ---------------- launcher --------------------------------------------------
#define GEMM_SMEM 73728
#define ATTN_SMEM 95744

extern "C" void kernel_launch(void* const* d_in, const int* in_sizes, int n_in,
                              void* d_out, int out_size)
{
    const float* nodes   = (const float*)d_in[0];
    const int*   dist    = (const int*)  d_in[1];
    const float* dense_w = (const float*)d_in[2];
    const float* dense_b = (const float*)d_in[3];
    const float* dln_g   = (const float*)d_in[4];
    const float* dln_b   = (const float*)d_in[5];
    const float* qkv_w   = (const float*)d_in[6];
    const float* qkv_b   = (const float*)d_in[7];
    const float* out_w   = (const float*)d_in[8];
    const float* out_b   = (const float*)d_in[9];
    const float* ln1_g   = (const float*)d_in[10];
    const float* ln1_b   = (const float*)d_in[11];
    const float* w1      = (const float*)d_in[12];
    const float* b1      = (const float*)d_in[13];
    const float* w2      = (const float*)d_in[14];
    const float* b2      = (const float*)d_in[15];
    const float* ln2_g   = (const float*)d_in[16];
    const float* ln2_b   = (const float*)d_in[17];
    const float* bn_g    = (const float*)d_in[18];
    const float* bn_b    = (const float*)d_in[19];
    float* out = (float*)d_out;

    __half *xin, *xc, *attn, *ff, *wbuf, *qkvh;
    float *x, *tmp;
    uint32_t* mask;
    cudaGetSymbolAddress((void**)&xin,  g_xin);
    cudaGetSymbolAddress((void**)&x,    g_x);
    cudaGetSymbolAddress((void**)&xc,   g_xc);
    cudaGetSymbolAddress((void**)&tmp,  g_tmp);
    cudaGetSymbolAddress((void**)&qkvh, g_qkvh);
    cudaGetSymbolAddress((void**)&attn, g_attn);
    cudaGetSymbolAddress((void**)&ff,   g_ff);
    cudaGetSymbolAddress((void**)&wbuf, g_w);
    cudaGetSymbolAddress((void**)&mask, g_mask);

    cudaFuncSetAttribute(gemm_f16, cudaFuncAttributeMaxDynamicSharedMemorySize, GEMM_SMEM);
    cudaFuncSetAttribute(attn_f16, cudaFuncAttributeMaxDynamicSharedMemorySize, ATTN_SMEM);

    // one-time-per-launch preprocessing
    cvt_all_kernel<<<8320, 256>>>((const float4*)dense_w, (const float4*)qkv_w,
                                  (const float4*)out_w, (const float4*)w1,
                                  (const float4*)w2, (uint2*)wbuf);
    mask_kernel<<<dim3(SLEN/8, BSZ), 256>>>(dist, mask);
    transpose_kernel<<<NTOK, IDIM>>>(nodes, xin);

    // dense + LN
    gemm_f16<<<dim3(HDIM/128, NTOK/128), 256, GEMM_SMEM>>>(
        xin, wbuf + OFF_DENSE, dense_b, tmp, NTOK, HDIM, IDIM, 0);
    ln_kernel<<<NTOK, 256>>>(tmp, nullptr, dln_g, dln_b, x, xc);

    for (int l = 0; l < NLAYER; l++) {
        // QKV projection -> fp16 Q|K|V
        gemm_f16<<<dim3(3*HDIM/128, NTOK/128), 256, GEMM_SMEM>>>(
            xc, wbuf + OFF_QKV + (size_t)l*3*HDIM*HDIM, qkv_b + (size_t)l*3*HDIM,
            qkvh, NTOK, 3*HDIM, HDIM, 4);
        attn_f16<<<dim3(SLEN/128, NHEAD, BSZ), 512, ATTN_SMEM>>>(qkvh, mask, attn);
        gemm_f16<<<dim3(HDIM/128, NTOK/128), 256, GEMM_SMEM>>>(
            attn, wbuf + OFF_OUT + (size_t)l*HDIM*HDIM, out_b + (size_t)l*HDIM,
            tmp, NTOK, HDIM, HDIM, 0);
        ln_kernel<<<NTOK, 256>>>(tmp, x, ln1_g + (size_t)l*HDIM,
                                 ln1_b + (size_t)l*HDIM, x, xc);
        gemm_f16<<<dim3(FFDIM/128, NTOK/128), 256, GEMM_SMEM>>>(
            xc, wbuf + OFF_FF1 + (size_t)l*FFDIM*HDIM, b1 + (size_t)l*FFDIM,
            ff, NTOK, FFDIM, HDIM, 5);
        gemm_f16<<<dim3(HDIM/128, NTOK/128), 256, GEMM_SMEM>>>(
            ff, wbuf + OFF_FF2 + (size_t)l*HDIM*FFDIM, b2 + (size_t)l*HDIM,
            tmp, NTOK, HDIM, FFDIM, 0);
        ln_kernel<<<NTOK, 256>>>(tmp, x, ln2_g + (size_t)l*HDIM,
                                 ln2_b + (size_t)l*HDIM, x, xc);
    }

    bn_kernel<<<1, HDIM>>>(x, bn_g, bn_b, out);
}

// round 14
// speedup vs baseline: 1.5224x; 1.5224x over previous
#include <cuda_runtime.h>
#include <cuda_fp16.h>
#include <math.h>
#include <stdint.h>

// Problem constants
#define SLEN 1024
#define BSZ  8
#define IDIM 256
#define HDIM 512
#define NHEAD 8
#define HD 64
#define FFDIM 1024
#define NLAYER 4
#define NTOK (SLEN*BSZ)   // 8192

// ---------------- scratch (device globals; no allocation allowed) -----------
__device__ __half g_xin [NTOK * IDIM];    // fp16
__device__ float  g_x   [NTOK * HDIM];    // fp32 (residual stream)
__device__ __half g_xc  [NTOK * HDIM];    // fp16 copy of x
__device__ float  g_tmp [NTOK * HDIM];    // fp32
__device__ __half g_qkvh[NTOK * 1536];    // fp16 Q|K|V
__device__ __half g_attn[NTOK * HDIM];    // fp16
__device__ __half g_ff  [NTOK * FFDIM];   // fp16
__device__ __half g_w   [8519680];        // all weights, fp16
__device__ uint32_t g_mask[3 * BSZ * SLEN * 32];  // packed allow-bits per class

// weight offsets in g_w (halves)
#define OFF_DENSE 0
#define OFF_QKV   131072
#define OFF_OUT   3276800
#define OFF_FF1   4325376
#define OFF_FF2   6422528

// ---------------- helpers ---------------------------------------------------
// fp16 mma: k=16, fp32 accumulate
__device__ __forceinline__ void mma16h(float* c, const uint32_t* a, uint32_t b0, uint32_t b1){
    asm volatile(
        "mma.sync.aligned.m16n8k16.row.col.f32.f16.f16.f32 "
        "{%0,%1,%2,%3},{%4,%5,%6,%7},{%8,%9},{%0,%1,%2,%3};"
        : "+f"(c[0]),"+f"(c[1]),"+f"(c[2]),"+f"(c[3])
        : "r"(a[0]),"r"(a[1]),"r"(a[2]),"r"(a[3]),"r"(b0),"r"(b1));
}
__device__ __forceinline__ void ldsm4t(uint32_t& r0, uint32_t& r1, uint32_t& r2, uint32_t& r3,
                                       uint32_t addr){
    asm volatile("ldmatrix.sync.aligned.m8n8.x4.trans.shared.b16 {%0,%1,%2,%3}, [%4];"
        : "=r"(r0),"=r"(r1),"=r"(r2),"=r"(r3) : "r"(addr));
}
__device__ __forceinline__ void cpa16(uint32_t s, const void* g){
    asm volatile("cp.async.cg.shared.global [%0], [%1], 16;" :: "r"(s),"l"(g));
}
__device__ __forceinline__ void cpacommit(){ asm volatile("cp.async.commit_group;"); }
__device__ __forceinline__ void cpawait1(){ asm volatile("cp.async.wait_group 1;"); }
__device__ __forceinline__ void cpawait0(){ asm volatile("cp.async.wait_group 0;"); }

// ---------------- all-weights fp16 conversion (one launch) ------------------
__global__ void cvt_all_kernel(const float4* __restrict__ s0, const float4* __restrict__ s1,
                               const float4* __restrict__ s2, const float4* __restrict__ s3,
                               const float4* __restrict__ s4, uint2* __restrict__ dst)
{
    int i = blockIdx.x * 256 + threadIdx.x;
    if (i >= 2129920) return;
    const float4* src;
    if      (i <   32768) src = s0 + i;
    else if (i <  819200) src = s1 + (i - 32768);
    else if (i < 1081344) src = s2 + (i - 819200);
    else if (i < 1605632) src = s3 + (i - 1081344);
    else                  src = s4 + (i - 1605632);
    float4 v = *src;
    __half2 h0 = __floats2half2_rn(v.x, v.y);
    __half2 h1 = __floats2half2_rn(v.z, v.w);
    uint2 o;
    o.x = *(uint32_t*)&h0;
    o.y = *(uint32_t*)&h1;
    dst[i] = o;
}

// ---------------- mask bit precompute ---------------------------------------
__global__ void mask_kernel(const int* __restrict__ dist, uint32_t* __restrict__ mask)
{
    int b = blockIdx.y;
    int q = blockIdx.x * 8 + (threadIdx.x >> 5);
    int w = threadIdx.x & 31;
    const int4* dr = (const int4*)(dist + ((size_t)b*SLEN + q)*SLEN + w*32);
    const int4* d0 = (const int4*)(dist + (size_t)b*SLEN*SLEN + w*32);
    uint32_t sb = 0, lb = 0, gb = 0;
#pragma unroll
    for (int p = 0; p < 8; p++){
        int4 d = dr[p], dg = d0[p];
        int j = p*4;
        sb |= (uint32_t)(d.x==1)<<j | (uint32_t)(d.y==1)<<(j+1)
            | (uint32_t)(d.z==1)<<(j+2) | (uint32_t)(d.w==1)<<(j+3);
        lb |= (uint32_t)(d.x>=1)<<j | (uint32_t)(d.y>=1)<<(j+1)
            | (uint32_t)(d.z>=1)<<(j+2) | (uint32_t)(d.w>=1)<<(j+3);
        gb |= (uint32_t)(dg.x>=1)<<j | (uint32_t)(dg.y>=1)<<(j+1)
            | (uint32_t)(dg.z>=1)<<(j+2) | (uint32_t)(dg.w>=1)<<(j+3);
    }
    if ((q >> 5) == w){ uint32_t e = 1u << (q & 31); sb |= e; lb |= e; gb |= e; }
    size_t o = ((size_t)b*SLEN + q)*32 + w;
    mask[o] = sb;
    mask[(size_t)BSZ*SLEN*32 + o] = lb;
    mask[(size_t)2*BSZ*SLEN*32 + o] = gb;
}

// ---------------- transpose nodes (S,B,I) -> x_in (B*S, I), fp16 ------------
__global__ void transpose_kernel(const float* __restrict__ nodes, __half* __restrict__ xin)
{
    int token = blockIdx.x;
    int b = token >> 10;
    int s = token & 1023;
    float v = nodes[((size_t)s * BSZ + b) * IDIM + threadIdx.x];
    xin[(size_t)token * IDIM + threadIdx.x] = __float2half_rn(v);
}

// ---------------- fp16 tensor-core GEMM: C[M,N] = A[M,K] @ W[N,K]^T + bias --
// CTA 128x128, BK=64 halves, 256 threads = 8 warps (2m x 4n), warp tile 64x32.
// flags: bit0 relu, bit2 store fp16 (else fp32).
__global__ __launch_bounds__(256,2) void gemm_f16(
    const __half* __restrict__ A, const __half* __restrict__ W,
    const float* __restrict__ bias, void* __restrict__ Cv,
    int M, int N, int K, int flags)
{
    extern __shared__ uint32_t smu[];
    uint32_t* sA = smu;             // 2 stages * 4608 u32
    uint32_t* sB = smu + 9216;      // 2 stages * 4608 u32

    const int tid  = threadIdx.x;
    const int lane = tid & 31, wid = tid >> 5;
    const int g = lane >> 2, r = lane & 3;
    const int wm = wid & 1, wn = wid >> 1;
    const int row0 = blockIdx.y * 128, col0 = blockIdx.x * 128;

    const uint32_t sAb = (uint32_t)__cvta_generic_to_shared(sA);
    const uint32_t sBb = (uint32_t)__cvta_generic_to_shared(sB);

    float c[4][4][4];
#pragma unroll
    for (int i=0;i<4;i++)
#pragma unroll
        for (int j=0;j<4;j++)
#pragma unroll
            for (int k=0;k<4;k++) c[i][j][k] = 0.f;

    const int nbk = K >> 6;

    auto issue = [&](int bk, int st){
#pragma unroll
        for (int p=0;p<4;p++){
            int idx = tid + p*256;
            int row = idx >> 3, c4 = (idx & 7) << 2;
            cpa16(sAb + (uint32_t)(st*4608 + row*36 + c4)*4,
                  A + (size_t)(row0 + row)*K + bk*64 + c4*2);
            cpa16(sBb + (uint32_t)(st*4608 + row*36 + c4)*4,
                  W + (size_t)(col0 + row)*K + bk*64 + c4*2);
        }
        cpacommit();
    };

    issue(0, 0);
    for (int bk = 0; bk < nbk; bk++){
        int st = bk & 1;
        if (bk+1 < nbk){ issue(bk+1, st^1); cpawait1(); }
        else           { cpawait0(); }
        __syncthreads();
        const uint32_t* a_s = sA + st*4608;
        const uint32_t* b_s = sB + st*4608;
#pragma unroll
        for (int kc=0; kc<4; kc++){
            uint32_t a[4][4];
#pragma unroll
            for (int mt=0; mt<4; mt++){
                int mb = wm*64 + mt*16;
                a[mt][0] = a_s[(mb+g  )*36 + kc*8 + r  ];
                a[mt][1] = a_s[(mb+g+8)*36 + kc*8 + r  ];
                a[mt][2] = a_s[(mb+g  )*36 + kc*8 + r+4];
                a[mt][3] = a_s[(mb+g+8)*36 + kc*8 + r+4];
            }
#pragma unroll
            for (int nt=0; nt<4; nt++){
                int nb = wn*32 + nt*8;
                uint32_t b0 = b_s[(nb+g)*36 + kc*8 + r  ];
                uint32_t b1 = b_s[(nb+g)*36 + kc*8 + r+4];
#pragma unroll
                for (int mt=0; mt<4; mt++) mma16h(c[mt][nt], a[mt], b0, b1);
            }
        }
        __syncthreads();
    }

    const int relu = flags & 1, hfo = flags & 4;
#pragma unroll
    for (int mt=0; mt<4; mt++){
#pragma unroll
        for (int nt=0; nt<4; nt++){
            int rr = row0 + wm*64 + mt*16 + g;
            int cc = col0 + wn*32 + nt*8 + 2*r;
            float b0 = bias[cc], b1 = bias[cc+1];
            float v0 = c[mt][nt][0] + b0, v1 = c[mt][nt][1] + b1;
            float v2 = c[mt][nt][2] + b0, v3 = c[mt][nt][3] + b1;
            if (relu){ v0=fmaxf(v0,0.f); v1=fmaxf(v1,0.f); v2=fmaxf(v2,0.f); v3=fmaxf(v3,0.f); }
            if (hfo){
                __half* Ch = (__half*)Cv;
                *(__half2*)(Ch + (size_t)rr*N + cc)     = __floats2half2_rn(v0, v1);
                *(__half2*)(Ch + (size_t)(rr+8)*N + cc) = __floats2half2_rn(v2, v3);
            } else {
                float* Cf = (float*)Cv;
                *(float2*)(Cf + (size_t)rr*N + cc)     = make_float2(v0, v1);
                *(float2*)(Cf + (size_t)(rr+8)*N + cc) = make_float2(v2, v3);
            }
        }
    }
}

// ---------------- LayerNorm row kernel (H=512), optional residual -----------
__global__ __launch_bounds__(256) void ln_kernel(
    const float* __restrict__ y, const float* __restrict__ res,
    const float* __restrict__ g, const float* __restrict__ bta,
    float* __restrict__ out, __half* __restrict__ outc)
{
    __shared__ float rs[8], rq[8], stats[2];
    int tid = threadIdx.x;
    int lane = tid & 31, wid = tid >> 5;
    size_t base = (size_t)blockIdx.x * HDIM;

    float v0 = y[base + tid];
    float v1 = y[base + tid + 256];
    if (res) { v0 += res[base + tid]; v1 += res[base + tid + 256]; }

    float sum = v0 + v1;
    float sq  = v0 * v0 + v1 * v1;
#pragma unroll
    for (int off = 16; off > 0; off >>= 1) {
        sum += __shfl_xor_sync(0xffffffffu, sum, off);
        sq  += __shfl_xor_sync(0xffffffffu, sq,  off);
    }
    if (lane == 0) { rs[wid] = sum; rq[wid] = sq; }
    __syncthreads();
    if (tid == 0) {
        float S = 0.f, Q = 0.f;
#pragma unroll
        for (int i = 0; i < 8; i++) { S += rs[i]; Q += rq[i]; }
        float mean = S * (1.0f / HDIM);
        float var  = Q * (1.0f / HDIM) - mean * mean;
        stats[0] = mean;
        stats[1] = rsqrtf(var + 1e-5f);
    }
    __syncthreads();
    float mean = stats[0], inv = stats[1];
    float o0 = (v0 - mean) * inv * g[tid]       + bta[tid];
    float o1 = (v1 - mean) * inv * g[tid + 256] + bta[tid + 256];
    out[base + tid]        = o0;
    out[base + tid + 256]  = o1;
    outc[base + tid]       = __float2half_rn(o0);
    outc[base + tid + 256] = __float2half_rn(o1);
}

// ---------------- flash attention: all-fp16 mma, fp32 softmax ---------------
// CTA: 128 q-rows, k-tiles of 128. 512 threads = 16 warps (8m x 2n).
// PV B-fragments via SOFTWARE-PIPELINED ldmatrix.trans (kc+1 issued before kc used).
__global__ __launch_bounds__(512,1) void attn_f16(
    const __half* __restrict__ qkvh, const uint32_t* __restrict__ maskall,
    __half* __restrict__ out)
{
    extern __shared__ uint32_t smx[];
    uint32_t* Qsu = smx;                      // 4608
    uint32_t* Ksu = smx + 4608;               // 4608
    uint32_t* Vsu = smx + 9216;               // 4608
    uint32_t* Msu = smx + 13824;              // 8704
    uint32_t* msku = smx + 22528;             // 512
    float* redm = (float*)(smx + 23040);      // 256
    float* reds = redm + 256;                 // 256
    float* rowM = reds + 256;                 // 128
    float* rowL = rowM + 128;                 // 128
    float* rowC = rowL + 128;                 // 128

    const int tid  = threadIdx.x;
    const int lane = tid & 31, wid = tid >> 5;
    const int g = lane >> 2, r = lane & 3;
    const int wm = wid & 7, wn = wid >> 3;
    const int q0 = blockIdx.x * 128, h = blockIdx.y, b = blockIdx.z;
    const size_t tokbase = (size_t)b * SLEN;
    const int qlo = wm*16 + g, qhi = qlo + 8;

    const int cls = (h < 4) ? 0 : (h < 6) ? 1 : 2;
    const uint32_t* mbase = maskall + (size_t)cls*BSZ*SLEN*32 + (size_t)b*SLEN*32;

    const uint32_t Qb = (uint32_t)__cvta_generic_to_shared(Qsu);
    const uint32_t Kb = (uint32_t)__cvta_generic_to_shared(Ksu);
    const uint32_t Vb = (uint32_t)__cvta_generic_to_shared(Vsu);

    // Q tile + K(0): 128 rows x 8 16B-chunks each
#pragma unroll
    for (int p=0;p<2;p++){
        int i = tid + p*512;
        int row = i >> 3, ch = i & 7;
        cpa16(Qb + (uint32_t)(row*36 + ch*4)*4,
              qkvh + (tokbase + q0 + row)*1536 + h*64 + ch*8);
        cpa16(Kb + (uint32_t)(row*36 + ch*4)*4,
              qkvh + (tokbase + row)*1536 + 512 + h*64 + ch*8);
    }
    cpacommit();
    if (tid < 128){ rowM[tid] = -1e30f; rowL[tid] = 0.f; }
    cpawait0();
    __syncthreads();

    // Q fragments, scaled by 1/sqrt(64) (exact exponent shift in fp16)
    const __half2 hs = __float2half2_rn(0.125f);
    uint32_t qa[4][4];
#pragma unroll
    for (int kc=0; kc<4; kc++){
#pragma unroll
        for (int j=0; j<4; j++){
            int rowq = (j & 1) ? qhi : qlo;
            int kk = kc*8 + r + ((j >> 1) ? 4 : 0);
            uint32_t u = Qsu[rowq*36 + kk];
            __half2 v = __hmul2(*(__half2*)&u, hs);
            qa[kc][j] = *(uint32_t*)&v;
        }
    }

    float o[4][4];
#pragma unroll
    for (int i=0;i<4;i++)
#pragma unroll
        for (int j=0;j<4;j++) o[i][j] = 0.f;

    const int lr = lane & 7, tt = lane >> 3;
    const int dc0 = wn*32 + (tt >> 1)*8;        // half-col base for this thread
    const int krb = (tt & 1)*8 + lr;            // k-row base within 16-group

    for (int t = 0; t < 8; t++){
        const int k0 = t * 128;

        msku[tid] = mbase[(size_t)(q0 + (tid >> 2))*32 + t*4 + (tid & 3)];

        // scores S[128x128] via fp16 mma (K(t) in Ksu)
        float s[8][4];
#pragma unroll
        for (int i=0;i<8;i++)
#pragma unroll
            for (int j=0;j<4;j++) s[i][j] = 0.f;
#pragma unroll
        for (int kc=0; kc<4; kc++){
#pragma unroll
            for (int nt=0; nt<8; nt++){
                int nb = wn*64 + nt*8;
                uint32_t b0 = Ksu[(nb+g)*36 + kc*8 + r  ];
                uint32_t b1 = Ksu[(nb+g)*36 + kc*8 + r+4];
                mma16h(s[nt], qa[kc], b0, b1);
            }
        }
        __syncthreads();   // S done (Ksu free), prev PV done (Vsu/Msu free), msku visible

        // prefetch V(t) and K(t+1) behind softmax
#pragma unroll
        for (int p=0;p<2;p++){
            int i = tid + p*512;
            int row = i >> 3, ch = i & 7;
            cpa16(Vb + (uint32_t)(row*36 + ch*4)*4,
                  qkvh + (tokbase + k0 + row)*1536 + 1024 + h*64 + ch*8);
        }
        if (t < 7){
#pragma unroll
            for (int p=0;p<2;p++){
                int i = tid + p*512;
                int row = i >> 3, ch = i & 7;
                cpa16(Kb + (uint32_t)(row*36 + ch*4)*4,
                      qkvh + (tokbase + k0 + 128 + row)*1536 + 512 + h*64 + ch*8);
            }
        }
        cpacommit();

        // mask apply (bit test) + per-row tile max
        uint32_t wl0 = msku[qlo*4 + wn*2], wl1 = msku[qlo*4 + wn*2 + 1];
        uint32_t wh0 = msku[qhi*4 + wn*2], wh1 = msku[qhi*4 + wn*2 + 1];
        float mx0 = -1e30f, mx1 = -1e30f;
#pragma unroll
        for (int nt=0; nt<8; nt++){
            uint32_t wlo = (nt < 4) ? wl0 : wl1;
            uint32_t whi = (nt < 4) ? wh0 : wh1;
            int sh = (nt & 3)*8 + 2*r;
            s[nt][0] = ((wlo >> sh)     & 1) ? s[nt][0] : -1e9f;
            s[nt][1] = ((wlo >> (sh+1)) & 1) ? s[nt][1] : -1e9f;
            s[nt][2] = ((whi >> sh)     & 1) ? s[nt][2] : -1e9f;
            s[nt][3] = ((whi >> (sh+1)) & 1) ? s[nt][3] : -1e9f;
            mx0 = fmaxf(mx0, fmaxf(s[nt][0], s[nt][1]));
            mx1 = fmaxf(mx1, fmaxf(s[nt][2], s[nt][3]));
        }
        mx0 = fmaxf(mx0, __shfl_xor_sync(0xffffffffu, mx0, 1));
        mx0 = fmaxf(mx0, __shfl_xor_sync(0xffffffffu, mx0, 2));
        mx1 = fmaxf(mx1, __shfl_xor_sync(0xffffffffu, mx1, 1));
        mx1 = fmaxf(mx1, __shfl_xor_sync(0xffffffffu, mx1, 2));
        if (r == 0){ redm[qlo*2 + wn] = mx0; redm[qhi*2 + wn] = mx1; }
        __syncthreads();
        if (tid < 128){
            float mo = rowM[tid];
            float mn = fmaxf(mo, fmaxf(redm[tid*2], redm[tid*2+1]));
            rowC[tid] = __expf(mo - mn);
            rowM[tid] = mn;
        }
        __syncthreads();

        // exp, write P (fp16 half2) to Ms, partial sums
        float mlo = rowM[qlo], mhi = rowM[qhi];
        float ps0 = 0.f, ps1 = 0.f;
#pragma unroll
        for (int nt=0; nt<8; nt++){
            int wofs = wn*32 + nt*4 + r;
            float p0 = __expf(s[nt][0]-mlo), p1 = __expf(s[nt][1]-mlo);
            float p2 = __expf(s[nt][2]-mhi), p3 = __expf(s[nt][3]-mhi);
            ps0 += p0 + p1;  ps1 += p2 + p3;
            __half2 hl = __floats2half2_rn(p0, p1);
            __half2 hh = __floats2half2_rn(p2, p3);
            Msu[qlo*68 + wofs] = *(uint32_t*)&hl;
            Msu[qhi*68 + wofs] = *(uint32_t*)&hh;
        }
        ps0 += __shfl_xor_sync(0xffffffffu, ps0, 1);
        ps0 += __shfl_xor_sync(0xffffffffu, ps0, 2);
        ps1 += __shfl_xor_sync(0xffffffffu, ps1, 1);
        ps1 += __shfl_xor_sync(0xffffffffu, ps1, 2);
        if (r == 0){ reds[qlo*2 + wn] = ps0; reds[qhi*2 + wn] = ps1; }

        // rescale O accumulators
        float clo = rowC[qlo], chi = rowC[qhi];
#pragma unroll
        for (int nt=0; nt<4; nt++){
            o[nt][0] *= clo; o[nt][1] *= clo;
            o[nt][2] *= chi; o[nt][3] *= chi;
        }
        cpawait0();        // V(t) and K(t+1) resident
        __syncthreads();   // V + P + reds visible
        if (tid < 128) rowL[tid] = rowL[tid]*rowC[tid] + reds[tid*2] + reds[tid*2+1];

        // O += P @ V : fp16 mma, pipelined ldmatrix.trans on V[k][d]
        {
            uint32_t bf[2][4], nf[2][4];
#pragma unroll
            for (int pr=0; pr<2; pr++)
                ldsm4t(bf[pr][0], bf[pr][1], bf[pr][2], bf[pr][3],
                       Vb + (uint32_t)(krb*36 + ((dc0 + pr*16) >> 1))*4);
#pragma unroll
            for (int kc=0; kc<8; kc++){
                uint32_t pa[4];
                pa[0] = Msu[qlo*68 + kc*8 + r  ];
                pa[1] = Msu[qhi*68 + kc*8 + r  ];
                pa[2] = Msu[qlo*68 + kc*8 + r+4];
                pa[3] = Msu[qhi*68 + kc*8 + r+4];
                if (kc < 7){
                    int kr = (kc+1)*16 + krb;
#pragma unroll
                    for (int pr=0; pr<2; pr++)
                        ldsm4t(nf[pr][0], nf[pr][1], nf[pr][2], nf[pr][3],
                               Vb + (uint32_t)(kr*36 + ((dc0 + pr*16) >> 1))*4);
                }
                mma16h(o[0], pa, bf[0][0], bf[0][1]);
                mma16h(o[1], pa, bf[0][2], bf[0][3]);
                mma16h(o[2], pa, bf[1][0], bf[1][1]);
                mma16h(o[3], pa, bf[1][2], bf[1][3]);
                if (kc < 7){
#pragma unroll
                    for (int pr=0; pr<2; pr++)
#pragma unroll
                        for (int j=0; j<4; j++) bf[pr][j] = nf[pr][j];
                }
            }
        }
    }
    __syncthreads();

    float llo = 1.f / rowL[qlo];
    float lhi = 1.f / rowL[qhi];
    size_t rlo = (tokbase + q0 + qlo) * HDIM;
    size_t rhi = (tokbase + q0 + qhi) * HDIM;
#pragma unroll
    for (int nt=0; nt<4; nt++){
        int cc = h*64 + wn*32 + nt*8 + 2*r;
        *(__half2*)(out + rlo + cc) = __floats2half2_rn(o[nt][0]*llo, o[nt][1]*llo);
        *(__half2*)(out + rhi + cc) = __floats2half2_rn(o[nt][2]*lhi, o[nt][3]*lhi);
    }
}

// ---------------- final batchnorm over batch of 8 at s=0 --------------------
__global__ void bn_kernel(const float* __restrict__ x, const float* __restrict__ g,
                          const float* __restrict__ bta, float* __restrict__ out)
{
    int c = threadIdx.x;
    float v[BSZ];
    float s = 0.f;
#pragma unroll
    for (int b = 0; b < BSZ; b++) {
        v[b] = x[((size_t)b * SLEN) * HDIM + c];
        s += v[b];
    }
    float mean = s * (1.0f / BSZ);
    float q = 0.f;
#pragma unroll
    for (int b = 0; b < BSZ; b++) { float d = v[b] - mean; q += d * d; }
    float inv = rsqrtf(q * (1.0f / BSZ) + 1e-5f);
#pragma unroll
    for (int b = 0; b < BSZ; b++)
        out[b * HDIM + c] = (v[b] - mean) * inv * g[c] + bta[c];
}

// ---------------- launcher --------------------------------------------------
#define GEMM_SMEM 73728
#define ATTN_SMEM 95744

extern "C" void kernel_launch(void* const* d_in, const int* in_sizes, int n_in,
                              void* d_out, int out_size)
{
    const float* nodes   = (const float*)d_in[0];
    const int*   dist    = (const int*)  d_in[1];
    const float* dense_w = (const float*)d_in[2];
    const float* dense_b = (const float*)d_in[3];
    const float* dln_g   = (const float*)d_in[4];
    const float* dln_b   = (const float*)d_in[5];
    const float* qkv_w   = (const float*)d_in[6];
    const float* qkv_b   = (const float*)d_in[7];
    const float* out_w   = (const float*)d_in[8];
    const float* out_b   = (const float*)d_in[9];
    const float* ln1_g   = (const float*)d_in[10];
    const float* ln1_b   = (const float*)d_in[11];
    const float* w1      = (const float*)d_in[12];
    const float* b1      = (const float*)d_in[13];
    const float* w2      = (const float*)d_in[14];
    const float* b2      = (const float*)d_in[15];
    const float* ln2_g   = (const float*)d_in[16];
    const float* ln2_b   = (const float*)d_in[17];
    const float* bn_g    = (const float*)d_in[18];
    const float* bn_b    = (const float*)d_in[19];
    float* out = (float*)d_out;

    __half *xin, *xc, *attn, *ff, *wbuf, *qkvh;
    float *x, *tmp;
    uint32_t* mask;
    cudaGetSymbolAddress((void**)&xin,  g_xin);
    cudaGetSymbolAddress((void**)&x,    g_x);
    cudaGetSymbolAddress((void**)&xc,   g_xc);
    cudaGetSymbolAddress((void**)&tmp,  g_tmp);
    cudaGetSymbolAddress((void**)&qkvh, g_qkvh);
    cudaGetSymbolAddress((void**)&attn, g_attn);
    cudaGetSymbolAddress((void**)&ff,   g_ff);
    cudaGetSymbolAddress((void**)&wbuf, g_w);
    cudaGetSymbolAddress((void**)&mask, g_mask);

    cudaFuncSetAttribute(gemm_f16, cudaFuncAttributeMaxDynamicSharedMemorySize, GEMM_SMEM);
    cudaFuncSetAttribute(attn_f16, cudaFuncAttributeMaxDynamicSharedMemorySize, ATTN_SMEM);

    // one-time-per-launch preprocessing
    cvt_all_kernel<<<8320, 256>>>((const float4*)dense_w, (const float4*)qkv_w,
                                  (const float4*)out_w, (const float4*)w1,
                                  (const float4*)w2, (uint2*)wbuf);
    mask_kernel<<<dim3(SLEN/8, BSZ), 256>>>(dist, mask);
    transpose_kernel<<<NTOK, IDIM>>>(nodes, xin);

    // dense + LN
    gemm_f16<<<dim3(HDIM/128, NTOK/128), 256, GEMM_SMEM>>>(
        xin, wbuf + OFF_DENSE, dense_b, tmp, NTOK, HDIM, IDIM, 0);
    ln_kernel<<<NTOK, 256>>>(tmp, nullptr, dln_g, dln_b, x, xc);

    for (int l = 0; l < NLAYER; l++) {
        gemm_f16<<<dim3(3*HDIM/128, NTOK/128), 256, GEMM_SMEM>>>(
            xc, wbuf + OFF_QKV + (size_t)l*3*HDIM*HDIM, qkv_b + (size_t)l*3*HDIM,
            qkvh, NTOK, 3*HDIM, HDIM, 4);
        attn_f16<<<dim3(SLEN/128, NHEAD, BSZ), 512, ATTN_SMEM>>>(qkvh, mask, attn);
        gemm_f16<<<dim3(HDIM/128, NTOK/128), 256, GEMM_SMEM>>>(
            attn, wbuf + OFF_OUT + (size_t)l*HDIM*HDIM, out_b + (size_t)l*HDIM,
            tmp, NTOK, HDIM, HDIM, 0);
        ln_kernel<<<NTOK, 256>>>(tmp, x, ln1_g + (size_t)l*HDIM,
                                 ln1_b + (size_t)l*HDIM, x, xc);
        gemm_f16<<<dim3(FFDIM/128, NTOK/128), 256, GEMM_SMEM>>>(
            xc, wbuf + OFF_FF1 + (size_t)l*FFDIM*HDIM, b1 + (size_t)l*FFDIM,
            ff, NTOK, FFDIM, HDIM, 5);
        gemm_f16<<<dim3(HDIM/128, NTOK/128), 256, GEMM_SMEM>>>(
            ff, wbuf + OFF_FF2 + (size_t)l*HDIM*FFDIM, b2 + (size_t)l*HDIM,
            tmp, NTOK, HDIM, FFDIM, 0);
        ln_kernel<<<NTOK, 256>>>(tmp, x, ln2_g + (size_t)l*HDIM,
                                 ln2_b + (size_t)l*HDIM, x, xc);
    }

    bn_kernel<<<1, HDIM>>>(x, bn_g, bn_b, out);
}

// round 16
// speedup vs baseline: 1.5504x; 1.0184x over previous
#include <cuda_runtime.h>
#include <cuda_fp16.h>
#include <math.h>
#include <stdint.h>

// Problem constants
#define SLEN 1024
#define BSZ  8
#define IDIM 256
#define HDIM 512
#define NHEAD 8
#define HD 64
#define FFDIM 1024
#define NLAYER 4
#define NTOK (SLEN*BSZ)   // 8192

// ---------------- scratch (device globals; no allocation allowed) -----------
__device__ __half g_xin [NTOK * IDIM];    // fp16
__device__ float  g_x   [NTOK * HDIM];    // fp32 (residual stream)
__device__ __half g_xc  [NTOK * HDIM];    // fp16 copy of x
__device__ float  g_tmp [NTOK * HDIM];    // fp32
__device__ __half g_qkvh[NTOK * 1536];    // fp16 Q|K|V
__device__ __half g_attn[NTOK * HDIM];    // fp16
__device__ __half g_ff  [NTOK * FFDIM];   // fp16
__device__ __half g_w   [8519680];        // all weights, fp16
__device__ uint32_t g_mask[3 * BSZ * SLEN * 32];  // packed allow-bits per class

// weight offsets in g_w (halves)
#define OFF_DENSE 0
#define OFF_QKV   131072
#define OFF_OUT   3276800
#define OFF_FF1   4325376
#define OFF_FF2   6422528

// ---------------- helpers ---------------------------------------------------
// fp16 mma: k=16, fp32 accumulate
__device__ __forceinline__ void mma16h(float* c, const uint32_t* a, uint32_t b0, uint32_t b1){
    asm volatile(
        "mma.sync.aligned.m16n8k16.row.col.f32.f16.f16.f32 "
        "{%0,%1,%2,%3},{%4,%5,%6,%7},{%8,%9},{%0,%1,%2,%3};"
        : "+f"(c[0]),"+f"(c[1]),"+f"(c[2]),"+f"(c[3])
        : "r"(a[0]),"r"(a[1]),"r"(a[2]),"r"(a[3]),"r"(b0),"r"(b1));
}
__device__ __forceinline__ void ldsm4t(uint32_t& r0, uint32_t& r1, uint32_t& r2, uint32_t& r3,
                                       uint32_t addr){
    asm volatile("ldmatrix.sync.aligned.m8n8.x4.trans.shared.b16 {%0,%1,%2,%3}, [%4];"
        : "=r"(r0),"=r"(r1),"=r"(r2),"=r"(r3) : "r"(addr));
}
__device__ __forceinline__ void cpa16(uint32_t s, const void* g){
    asm volatile("cp.async.cg.shared.global [%0], [%1], 16;" :: "r"(s),"l"(g));
}
__device__ __forceinline__ void cpacommit(){ asm volatile("cp.async.commit_group;"); }
__device__ __forceinline__ void cpawait1(){ asm volatile("cp.async.wait_group 1;"); }
__device__ __forceinline__ void cpawait0(){ asm volatile("cp.async.wait_group 0;"); }

// ---------------- all-weights fp16 conversion (one launch) ------------------
__global__ void cvt_all_kernel(const float4* __restrict__ s0, const float4* __restrict__ s1,
                               const float4* __restrict__ s2, const float4* __restrict__ s3,
                               const float4* __restrict__ s4, uint2* __restrict__ dst)
{
    int i = blockIdx.x * 256 + threadIdx.x;
    if (i >= 2129920) return;
    const float4* src;
    if      (i <   32768) src = s0 + i;
    else if (i <  819200) src = s1 + (i - 32768);
    else if (i < 1081344) src = s2 + (i - 819200);
    else if (i < 1605632) src = s3 + (i - 1081344);
    else                  src = s4 + (i - 1605632);
    float4 v = *src;
    __half2 h0 = __floats2half2_rn(v.x, v.y);
    __half2 h1 = __floats2half2_rn(v.z, v.w);
    uint2 o;
    o.x = *(uint32_t*)&h0;
    o.y = *(uint32_t*)&h1;
    dst[i] = o;
}

// ---------------- mask bit precompute ---------------------------------------
__global__ void mask_kernel(const int* __restrict__ dist, uint32_t* __restrict__ mask)
{
    int b = blockIdx.y;
    int q = blockIdx.x * 8 + (threadIdx.x >> 5);
    int w = threadIdx.x & 31;
    const int4* dr = (const int4*)(dist + ((size_t)b*SLEN + q)*SLEN + w*32);
    const int4* d0 = (const int4*)(dist + (size_t)b*SLEN*SLEN + w*32);
    uint32_t sb = 0, lb = 0, gb = 0;
#pragma unroll
    for (int p = 0; p < 8; p++){
        int4 d = dr[p], dg = d0[p];
        int j = p*4;
        sb |= (uint32_t)(d.x==1)<<j | (uint32_t)(d.y==1)<<(j+1)
            | (uint32_t)(d.z==1)<<(j+2) | (uint32_t)(d.w==1)<<(j+3);
        lb |= (uint32_t)(d.x>=1)<<j | (uint32_t)(d.y>=1)<<(j+1)
            | (uint32_t)(d.z>=1)<<(j+2) | (uint32_t)(d.w>=1)<<(j+3);
        gb |= (uint32_t)(dg.x>=1)<<j | (uint32_t)(dg.y>=1)<<(j+1)
            | (uint32_t)(dg.z>=1)<<(j+2) | (uint32_t)(dg.w>=1)<<(j+3);
    }
    if ((q >> 5) == w){ uint32_t e = 1u << (q & 31); sb |= e; lb |= e; gb |= e; }
    size_t o = ((size_t)b*SLEN + q)*32 + w;
    mask[o] = sb;
    mask[(size_t)BSZ*SLEN*32 + o] = lb;
    mask[(size_t)2*BSZ*SLEN*32 + o] = gb;
}

// ---------------- transpose nodes (S,B,I) -> x_in (B*S, I), fp16 ------------
__global__ void transpose_kernel(const float* __restrict__ nodes, __half* __restrict__ xin)
{
    int token = blockIdx.x;
    int b = token >> 10;
    int s = token & 1023;
    float v = nodes[((size_t)s * BSZ + b) * IDIM + threadIdx.x];
    xin[(size_t)token * IDIM + threadIdx.x] = __float2half_rn(v);
}

// ---------------- fp16 tensor-core GEMM: C[M,N] = A[M,K] @ W[N,K]^T + bias --
// CTA 128x128, BK=64 halves, 256 threads = 8 warps (2m x 4n), warp tile 64x32.
// 3-stage cp.async ring, ONE __syncthreads per stage (2 fills always in flight).
// flags: bit0 relu, bit2 store fp16 (else fp32).
__global__ __launch_bounds__(256,2) void gemm_f16(
    const __half* __restrict__ A, const __half* __restrict__ W,
    const float* __restrict__ bias, void* __restrict__ Cv,
    int M, int N, int K, int flags)
{
    extern __shared__ uint32_t smu[];   // 3 stages * 9216 u32 (A 4608 + B 4608)

    const int tid  = threadIdx.x;
    const int lane = tid & 31, wid = tid >> 5;
    const int g = lane >> 2, r = lane & 3;
    const int wm = wid & 1, wn = wid >> 1;
    const int row0 = blockIdx.y * 128, col0 = blockIdx.x * 128;

    const uint32_t sBase = (uint32_t)__cvta_generic_to_shared(smu);

    float c[4][4][4];
#pragma unroll
    for (int i=0;i<4;i++)
#pragma unroll
        for (int j=0;j<4;j++)
#pragma unroll
            for (int k=0;k<4;k++) c[i][j][k] = 0.f;

    const int nbk = K >> 6;

    auto issue = [&](int bk, int st){
        const uint32_t sAb = sBase + (uint32_t)st*36864;
        const uint32_t sBb = sAb + 18432;
#pragma unroll
        for (int p=0;p<4;p++){
            int idx = tid + p*256;
            int row = idx >> 3, c4 = (idx & 7) << 2;
            cpa16(sAb + (uint32_t)(row*36 + c4)*4,
                  A + (size_t)(row0 + row)*K + bk*64 + c4*2);
            cpa16(sBb + (uint32_t)(row*36 + c4)*4,
                  W + (size_t)(col0 + row)*K + bk*64 + c4*2);
        }
        cpacommit();
    };

    issue(0, 0);
    if (nbk > 1) issue(1, 1);

    for (int bk = 0; bk < nbk; bk++){
        if (bk + 1 < nbk) cpawait1();   // FIFO: stage bk resident, bk+1 may remain in flight
        else              cpawait0();
        __syncthreads();                // covers RAW (fill->read) and WAR (read(bk-1)->refill)
        if (bk + 2 < nbk) issue(bk + 2, (bk + 2) % 3);

        const int st = bk % 3;
        const uint32_t* a_s = smu + st*9216;
        const uint32_t* b_s = a_s + 4608;
#pragma unroll
        for (int kc=0; kc<4; kc++){
            uint32_t a[4][4];
#pragma unroll
            for (int mt=0; mt<4; mt++){
                int mb = wm*64 + mt*16;
                a[mt][0] = a_s[(mb+g  )*36 + kc*8 + r  ];
                a[mt][1] = a_s[(mb+g+8)*36 + kc*8 + r  ];
                a[mt][2] = a_s[(mb+g  )*36 + kc*8 + r+4];
                a[mt][3] = a_s[(mb+g+8)*36 + kc*8 + r+4];
            }
#pragma unroll
            for (int nt=0; nt<4; nt++){
                int nb = wn*32 + nt*8;
                uint32_t b0 = b_s[(nb+g)*36 + kc*8 + r  ];
                uint32_t b1 = b_s[(nb+g)*36 + kc*8 + r+4];
#pragma unroll
                for (int mt=0; mt<4; mt++) mma16h(c[mt][nt], a[mt], b0, b1);
            }
        }
    }

    const int relu = flags & 1, hfo = flags & 4;
#pragma unroll
    for (int mt=0; mt<4; mt++){
#pragma unroll
        for (int nt=0; nt<4; nt++){
            int rr = row0 + wm*64 + mt*16 + g;
            int cc = col0 + wn*32 + nt*8 + 2*r;
            float b0 = bias[cc], b1 = bias[cc+1];
            float v0 = c[mt][nt][0] + b0, v1 = c[mt][nt][1] + b1;
            float v2 = c[mt][nt][2] + b0, v3 = c[mt][nt][3] + b1;
            if (relu){ v0=fmaxf(v0,0.f); v1=fmaxf(v1,0.f); v2=fmaxf(v2,0.f); v3=fmaxf(v3,0.f); }
            if (hfo){
                __half* Ch = (__half*)Cv;
                *(__half2*)(Ch + (size_t)rr*N + cc)     = __floats2half2_rn(v0, v1);
                *(__half2*)(Ch + (size_t)(rr+8)*N + cc) = __floats2half2_rn(v2, v3);
            } else {
                float* Cf = (float*)Cv;
                *(float2*)(Cf + (size_t)rr*N + cc)     = make_float2(v0, v1);
                *(float2*)(Cf + (size_t)(rr+8)*N + cc) = make_float2(v2, v3);
            }
        }
    }
}

// ---------------- LayerNorm row kernel (H=512), optional residual -----------
__global__ __launch_bounds__(256) void ln_kernel(
    const float* __restrict__ y, const float* __restrict__ res,
    const float* __restrict__ g, const float* __restrict__ bta,
    float* __restrict__ out, __half* __restrict__ outc)
{
    __shared__ float rs[8], rq[8], stats[2];
    int tid = threadIdx.x;
    int lane = tid & 31, wid = tid >> 5;
    size_t base = (size_t)blockIdx.x * HDIM;

    float v0 = y[base + tid];
    float v1 = y[base + tid + 256];
    if (res) { v0 += res[base + tid]; v1 += res[base + tid + 256]; }

    float sum = v0 + v1;
    float sq  = v0 * v0 + v1 * v1;
#pragma unroll
    for (int off = 16; off > 0; off >>= 1) {
        sum += __shfl_xor_sync(0xffffffffu, sum, off);
        sq  += __shfl_xor_sync(0xffffffffu, sq,  off);
    }
    if (lane == 0) { rs[wid] = sum; rq[wid] = sq; }
    __syncthreads();
    if (tid == 0) {
        float S = 0.f, Q = 0.f;
#pragma unroll
        for (int i = 0; i < 8; i++) { S += rs[i]; Q += rq[i]; }
        float mean = S * (1.0f / HDIM);
        float var  = Q * (1.0f / HDIM) - mean * mean;
        stats[0] = mean;
        stats[1] = rsqrtf(var + 1e-5f);
    }
    __syncthreads();
    float mean = stats[0], inv = stats[1];
    float o0 = (v0 - mean) * inv * g[tid]       + bta[tid];
    float o1 = (v1 - mean) * inv * g[tid + 256] + bta[tid + 256];
    out[base + tid]        = o0;
    out[base + tid + 256]  = o1;
    outc[base + tid]       = __float2half_rn(o0);
    outc[base + tid + 256] = __float2half_rn(o1);
}

// ---------------- flash attention: all-fp16 mma, fp32 softmax ---------------
// CTA: 128 q-rows, k-tiles of 128. 512 threads = 16 warps (8m x 2n).
// PV B-fragments via SOFTWARE-PIPELINED ldmatrix.trans (kc+1 issued before kc used).
__global__ __launch_bounds__(512,1) void attn_f16(
    const __half* __restrict__ qkvh, const uint32_t* __restrict__ maskall,
    __half* __restrict__ out)
{
    extern __shared__ uint32_t smx[];
    uint32_t* Qsu = smx;                      // 4608
    uint32_t* Ksu = smx + 4608;               // 4608
    uint32_t* Vsu = smx + 9216;               // 4608
    uint32_t* Msu = smx + 13824;              // 8704
    uint32_t* msku = smx + 22528;             // 512
    float* redm = (float*)(smx + 23040);      // 256
    float* reds = redm + 256;                 // 256
    float* rowM = reds + 256;                 // 128
    float* rowL = rowM + 128;                 // 128
    float* rowC = rowL + 128;                 // 128

    const int tid  = threadIdx.x;
    const int lane = tid & 31, wid = tid >> 5;
    const int g = lane >> 2, r = lane & 3;
    const int wm = wid & 7, wn = wid >> 3;
    const int q0 = blockIdx.x * 128, h = blockIdx.y, b = blockIdx.z;
    const size_t tokbase = (size_t)b * SLEN;
    const int qlo = wm*16 + g, qhi = qlo + 8;

    const int cls = (h < 4) ? 0 : (h < 6) ? 1 : 2;
    const uint32_t* mbase = maskall + (size_t)cls*BSZ*SLEN*32 + (size_t)b*SLEN*32;

    const uint32_t Qb = (uint32_t)__cvta_generic_to_shared(Qsu);
    const uint32_t Kb = (uint32_t)__cvta_generic_to_shared(Ksu);
    const uint32_t Vb = (uint32_t)__cvta_generic_to_shared(Vsu);

    // Q tile + K(0): 128 rows x 8 16B-chunks each
#pragma unroll
    for (int p=0;p<2;p++){
        int i = tid + p*512;
        int row = i >> 3, ch = i & 7;
        cpa16(Qb + (uint32_t)(row*36 + ch*4)*4,
              qkvh + (tokbase + q0 + row)*1536 + h*64 + ch*8);
        cpa16(Kb + (uint32_t)(row*36 + ch*4)*4,
              qkvh + (tokbase + row)*1536 + 512 + h*64 + ch*8);
    }
    cpacommit();
    if (tid < 128){ rowM[tid] = -1e30f; rowL[tid] = 0.f; }
    cpawait0();
    __syncthreads();

    // Q fragments, scaled by 1/sqrt(64) (exact exponent shift in fp16)
    const __half2 hs = __float2half2_rn(0.125f);
    uint32_t qa[4][4];
#pragma unroll
    for (int kc=0; kc<4; kc++){
#pragma unroll
        for (int j=0; j<4; j++){
            int rowq = (j & 1) ? qhi : qlo;
            int kk = kc*8 + r + ((j >> 1) ? 4 : 0);
            uint32_t u = Qsu[rowq*36 + kk];
            __half2 v = __hmul2(*(__half2*)&u, hs);
            qa[kc][j] = *(uint32_t*)&v;
        }
    }

    float o[4][4];
#pragma unroll
    for (int i=0;i<4;i++)
#pragma unroll
        for (int j=0;j<4;j++) o[i][j] = 0.f;

    const int lr = lane & 7, tt = lane >> 3;
    const int dc0 = wn*32 + (tt >> 1)*8;        // half-col base for this thread
    const int krb = (tt & 1)*8 + lr;            // k-row base within 16-group

    for (int t = 0; t < 8; t++){
        const int k0 = t * 128;

        msku[tid] = mbase[(size_t)(q0 + (tid >> 2))*32 + t*4 + (tid & 3)];

        // scores S[128x128] via fp16 mma (K(t) in Ksu)
        float s[8][4];
#pragma unroll
        for (int i=0;i<8;i++)
#pragma unroll
            for (int j=0;j<4;j++) s[i][j] = 0.f;
#pragma unroll
        for (int kc=0; kc<4; kc++){
#pragma unroll
            for (int nt=0; nt<8; nt++){
                int nb = wn*64 + nt*8;
                uint32_t b0 = Ksu[(nb+g)*36 + kc*8 + r  ];
                uint32_t b1 = Ksu[(nb+g)*36 + kc*8 + r+4];
                mma16h(s[nt], qa[kc], b0, b1);
            }
        }
        __syncthreads();   // S done (Ksu free), prev PV done (Vsu/Msu free), msku visible

        // prefetch V(t) and K(t+1) behind softmax
#pragma unroll
        for (int p=0;p<2;p++){
            int i = tid + p*512;
            int row = i >> 3, ch = i & 7;
            cpa16(Vb + (uint32_t)(row*36 + ch*4)*4,
                  qkvh + (tokbase + k0 + row)*1536 + 1024 + h*64 + ch*8);
        }
        if (t < 7){
#pragma unroll
            for (int p=0;p<2;p++){
                int i = tid + p*512;
                int row = i >> 3, ch = i & 7;
                cpa16(Kb + (uint32_t)(row*36 + ch*4)*4,
                      qkvh + (tokbase + k0 + 128 + row)*1536 + 512 + h*64 + ch*8);
            }
        }
        cpacommit();

        // mask apply (bit test) + per-row tile max
        uint32_t wl0 = msku[qlo*4 + wn*2], wl1 = msku[qlo*4 + wn*2 + 1];
        uint32_t wh0 = msku[qhi*4 + wn*2], wh1 = msku[qhi*4 + wn*2 + 1];
        float mx0 = -1e30f, mx1 = -1e30f;
#pragma unroll
        for (int nt=0; nt<8; nt++){
            uint32_t wlo = (nt < 4) ? wl0 : wl1;
            uint32_t whi = (nt < 4) ? wh0 : wh1;
            int sh = (nt & 3)*8 + 2*r;
            s[nt][0] = ((wlo >> sh)     & 1) ? s[nt][0] : -1e9f;
            s[nt][1] = ((wlo >> (sh+1)) & 1) ? s[nt][1] : -1e9f;
            s[nt][2] = ((whi >> sh)     & 1) ? s[nt][2] : -1e9f;
            s[nt][3] = ((whi >> (sh+1)) & 1) ? s[nt][3] : -1e9f;
            mx0 = fmaxf(mx0, fmaxf(s[nt][0], s[nt][1]));
            mx1 = fmaxf(mx1, fmaxf(s[nt][2], s[nt][3]));
        }
        mx0 = fmaxf(mx0, __shfl_xor_sync(0xffffffffu, mx0, 1));
        mx0 = fmaxf(mx0, __shfl_xor_sync(0xffffffffu, mx0, 2));
        mx1 = fmaxf(mx1, __shfl_xor_sync(0xffffffffu, mx1, 1));
        mx1 = fmaxf(mx1, __shfl_xor_sync(0xffffffffu, mx1, 2));
        if (r == 0){ redm[qlo*2 + wn] = mx0; redm[qhi*2 + wn] = mx1; }
        __syncthreads();
        if (tid < 128){
            float mo = rowM[tid];
            float mn = fmaxf(mo, fmaxf(redm[tid*2], redm[tid*2+1]));
            rowC[tid] = __expf(mo - mn);
            rowM[tid] = mn;
        }
        __syncthreads();

        // exp, write P (fp16 half2) to Ms, partial sums
        float mlo = rowM[qlo], mhi = rowM[qhi];
        float ps0 = 0.f, ps1 = 0.f;
#pragma unroll
        for (int nt=0; nt<8; nt++){
            int wofs = wn*32 + nt*4 + r;
            float p0 = __expf(s[nt][0]-mlo), p1 = __expf(s[nt][1]-mlo);
            float p2 = __expf(s[nt][2]-mhi), p3 = __expf(s[nt][3]-mhi);
            ps0 += p0 + p1;  ps1 += p2 + p3;
            __half2 hl = __floats2half2_rn(p0, p1);
            __half2 hh = __floats2half2_rn(p2, p3);
            Msu[qlo*68 + wofs] = *(uint32_t*)&hl;
            Msu[qhi*68 + wofs] = *(uint32_t*)&hh;
        }
        ps0 += __shfl_xor_sync(0xffffffffu, ps0, 1);
        ps0 += __shfl_xor_sync(0xffffffffu, ps0, 2);
        ps1 += __shfl_xor_sync(0xffffffffu, ps1, 1);
        ps1 += __shfl_xor_sync(0xffffffffu, ps1, 2);
        if (r == 0){ reds[qlo*2 + wn] = ps0; reds[qhi*2 + wn] = ps1; }

        // rescale O accumulators
        float clo = rowC[qlo], chi = rowC[qhi];
#pragma unroll
        for (int nt=0; nt<4; nt++){
            o[nt][0] *= clo; o[nt][1] *= clo;
            o[nt][2] *= chi; o[nt][3] *= chi;
        }
        cpawait0();        // V(t) and K(t+1) resident
        __syncthreads();   // V + P + reds visible
        if (tid < 128) rowL[tid] = rowL[tid]*rowC[tid] + reds[tid*2] + reds[tid*2+1];

        // O += P @ V : fp16 mma, pipelined ldmatrix.trans on V[k][d]
        {
            uint32_t bf[2][4], nf[2][4];
#pragma unroll
            for (int pr=0; pr<2; pr++)
                ldsm4t(bf[pr][0], bf[pr][1], bf[pr][2], bf[pr][3],
                       Vb + (uint32_t)(krb*36 + ((dc0 + pr*16) >> 1))*4);
#pragma unroll
            for (int kc=0; kc<8; kc++){
                uint32_t pa[4];
                pa[0] = Msu[qlo*68 + kc*8 + r  ];
                pa[1] = Msu[qhi*68 + kc*8 + r  ];
                pa[2] = Msu[qlo*68 + kc*8 + r+4];
                pa[3] = Msu[qhi*68 + kc*8 + r+4];
                if (kc < 7){
                    int kr = (kc+1)*16 + krb;
#pragma unroll
                    for (int pr=0; pr<2; pr++)
                        ldsm4t(nf[pr][0], nf[pr][1], nf[pr][2], nf[pr][3],
                               Vb + (uint32_t)(kr*36 + ((dc0 + pr*16) >> 1))*4);
                }
                mma16h(o[0], pa, bf[0][0], bf[0][1]);
                mma16h(o[1], pa, bf[0][2], bf[0][3]);
                mma16h(o[2], pa, bf[1][0], bf[1][1]);
                mma16h(o[3], pa, bf[1][2], bf[1][3]);
                if (kc < 7){
#pragma unroll
                    for (int pr=0; pr<2; pr++)
#pragma unroll
                        for (int j=0; j<4; j++) bf[pr][j] = nf[pr][j];
                }
            }
        }
    }
    __syncthreads();

    float llo = 1.f / rowL[qlo];
    float lhi = 1.f / rowL[qhi];
    size_t rlo = (tokbase + q0 + qlo) * HDIM;
    size_t rhi = (tokbase + q0 + qhi) * HDIM;
#pragma unroll
    for (int nt=0; nt<4; nt++){
        int cc = h*64 + wn*32 + nt*8 + 2*r;
        *(__half2*)(out + rlo + cc) = __floats2half2_rn(o[nt][0]*llo, o[nt][1]*llo);
        *(__half2*)(out + rhi + cc) = __floats2half2_rn(o[nt][2]*lhi, o[nt][3]*lhi);
    }
}

// ---------------- final batchnorm over batch of 8 at s=0 --------------------
__global__ void bn_kernel(const float* __restrict__ x, const float* __restrict__ g,
                          const float* __restrict__ bta, float* __restrict__ out)
{
    int c = threadIdx.x;
    float v[BSZ];
    float s = 0.f;
#pragma unroll
    for (int b = 0; b < BSZ; b++) {
        v[b] = x[((size_t)b * SLEN) * HDIM + c];
        s += v[b];
    }
    float mean = s * (1.0f / BSZ);
    float q = 0.f;
#pragma unroll
    for (int b = 0; b < BSZ; b++) { float d = v[b] - mean; q += d * d; }
    float inv = rsqrtf(q * (1.0f / BSZ) + 1e-5f);
#pragma unroll
    for (int b = 0; b < BSZ; b++)
        out[b * HDIM + c] = (v[b] - mean) * inv * g[c] + bta[c];
}

// ---------------- launcher --------------------------------------------------
#define GEMM_SMEM 110592
#define ATTN_SMEM 95744

extern "C" void kernel_launch(void* const* d_in, const int* in_sizes, int n_in,
                              void* d_out, int out_size)
{
    const float* nodes   = (const float*)d_in[0];
    const int*   dist    = (const int*)  d_in[1];
    const float* dense_w = (const float*)d_in[2];
    const float* dense_b = (const float*)d_in[3];
    const float* dln_g   = (const float*)d_in[4];
    const float* dln_b   = (const float*)d_in[5];
    const float* qkv_w   = (const float*)d_in[6];
    const float* qkv_b   = (const float*)d_in[7];
    const float* out_w   = (const float*)d_in[8];
    const float* out_b   = (const float*)d_in[9];
    const float* ln1_g   = (const float*)d_in[10];
    const float* ln1_b   = (const float*)d_in[11];
    const float* w1      = (const float*)d_in[12];
    const float* b1      = (const float*)d_in[13];
    const float* w2      = (const float*)d_in[14];
    const float* b2      = (const float*)d_in[15];
    const float* ln2_g   = (const float*)d_in[16];
    const float* ln2_b   = (const float*)d_in[17];
    const float* bn_g    = (const float*)d_in[18];
    const float* bn_b    = (const float*)d_in[19];
    float* out = (float*)d_out;

    __half *xin, *xc, *attn, *ff, *wbuf, *qkvh;
    float *x, *tmp;
    uint32_t* mask;
    cudaGetSymbolAddress((void**)&xin,  g_xin);
    cudaGetSymbolAddress((void**)&x,    g_x);
    cudaGetSymbolAddress((void**)&xc,   g_xc);
    cudaGetSymbolAddress((void**)&tmp,  g_tmp);
    cudaGetSymbolAddress((void**)&qkvh, g_qkvh);
    cudaGetSymbolAddress((void**)&attn, g_attn);
    cudaGetSymbolAddress((void**)&ff,   g_ff);
    cudaGetSymbolAddress((void**)&wbuf, g_w);
    cudaGetSymbolAddress((void**)&mask, g_mask);

    cudaFuncSetAttribute(gemm_f16, cudaFuncAttributeMaxDynamicSharedMemorySize, GEMM_SMEM);
    cudaFuncSetAttribute(attn_f16, cudaFuncAttributeMaxDynamicSharedMemorySize, ATTN_SMEM);

    // one-time-per-launch preprocessing
    cvt_all_kernel<<<8320, 256>>>((const float4*)dense_w, (const float4*)qkv_w,
                                  (const float4*)out_w, (const float4*)w1,
                                  (const float4*)w2, (uint2*)wbuf);
    mask_kernel<<<dim3(SLEN/8, BSZ), 256>>>(dist, mask);
    transpose_kernel<<<NTOK, IDIM>>>(nodes, xin);

    // dense + LN
    gemm_f16<<<dim3(HDIM/128, NTOK/128), 256, GEMM_SMEM>>>(
        xin, wbuf + OFF_DENSE, dense_b, tmp, NTOK, HDIM, IDIM, 0);
    ln_kernel<<<NTOK, 256>>>(tmp, nullptr, dln_g, dln_b, x, xc);

    for (int l = 0; l < NLAYER; l++) {
        gemm_f16<<<dim3(3*HDIM/128, NTOK/128), 256, GEMM_SMEM>>>(
            xc, wbuf + OFF_QKV + (size_t)l*3*HDIM*HDIM, qkv_b + (size_t)l*3*HDIM,
            qkvh, NTOK, 3*HDIM, HDIM, 4);
        attn_f16<<<dim3(SLEN/128, NHEAD, BSZ), 512, ATTN_SMEM>>>(qkvh, mask, attn);
        gemm_f16<<<dim3(HDIM/128, NTOK/128), 256, GEMM_SMEM>>>(
            attn, wbuf + OFF_OUT + (size_t)l*HDIM*HDIM, out_b + (size_t)l*HDIM,
            tmp, NTOK, HDIM, HDIM, 0);
        ln_kernel<<<NTOK, 256>>>(tmp, x, ln1_g + (size_t)l*HDIM,
                                 ln1_b + (size_t)l*HDIM, x, xc);
        gemm_f16<<<dim3(FFDIM/128, NTOK/128), 256, GEMM_SMEM>>>(
            xc, wbuf + OFF_FF1 + (size_t)l*FFDIM*HDIM, b1 + (size_t)l*FFDIM,
            ff, NTOK, FFDIM, HDIM, 5);
        gemm_f16<<<dim3(HDIM/128, NTOK/128), 256, GEMM_SMEM>>>(
            ff, wbuf + OFF_FF2 + (size_t)l*HDIM*FFDIM, b2 + (size_t)l*HDIM,
            tmp, NTOK, HDIM, FFDIM, 0);
        ln_kernel<<<NTOK, 256>>>(tmp, x, ln2_g + (size_t)l*HDIM,
                                 ln2_b + (size_t)l*HDIM, x, xc);
    }

    bn_kernel<<<1, HDIM>>>(x, bn_g, bn_b, out);
}